// round 14
// baseline (speedup 1.0000x reference)
#include <cuda_runtime.h>
#include <cuda_bf16.h>
#include <cuda_fp16.h>
#include <cstdint>

// Problem constants
#define BMAXR 32768
#define DDIM  1024
#define TTREE 8
#define NODES 63
#define LEAVES 64
#define NPAD  512
#define ODIM  128

// Scratch (static device globals -- no runtime allocation)
__device__ __align__(256) __half  g_Bt[(size_t)NPAD * DDIM];      // fp16 W [n][k]
__device__ __align__(256) __half  g_mu[(size_t)BMAXR * NPAD];     // fp16 mu
__device__ __align__(256) __half  g_LBh[(size_t)ODIM * NPAD];     // fp16 LW [o][k]

// ===========================================================================
// PTX helpers (all arch-generic: sm_80+ / sm_75+)
// ===========================================================================
__device__ __forceinline__ uint32_t smem_u32(const void* p) {
    uint32_t a;
    asm("{ .reg .u64 t; cvta.to.shared.u64 t, %1; cvt.u32.u64 %0, t; }"
        : "=r"(a) : "l"(p));
    return a;
}
__device__ __forceinline__ void cp16(uint32_t dst, const void* src) {
    asm volatile("cp.async.cg.shared.global [%0], [%1], 16;"
                 :: "r"(dst), "l"(src) : "memory");
}
#define CP_COMMIT() asm volatile("cp.async.commit_group;" ::: "memory")
#define CP_WAIT(n)  asm volatile("cp.async.wait_group %0;" :: "n"(n) : "memory")

__device__ __forceinline__ void ldsm4(uint32_t& r0, uint32_t& r1,
                                      uint32_t& r2, uint32_t& r3, uint32_t addr) {
    asm volatile("ldmatrix.sync.aligned.m8n8.x4.shared.b16 {%0,%1,%2,%3}, [%4];"
                 : "=r"(r0), "=r"(r1), "=r"(r2), "=r"(r3) : "r"(addr));
}
__device__ __forceinline__ void lds128f(float4& v, uint32_t a) {
    asm volatile("ld.shared.v4.f32 {%0,%1,%2,%3}, [%4];"
                 : "=f"(v.x), "=f"(v.y), "=f"(v.z), "=f"(v.w) : "r"(a));
}
__device__ __forceinline__ void sts128(uint32_t a, uint32_t r0, uint32_t r1,
                                       uint32_t r2, uint32_t r3) {
    asm volatile("st.shared.v4.b32 [%0], {%1,%2,%3,%4};"
                 :: "r"(a), "r"(r0), "r"(r1), "r"(r2), "r"(r3) : "memory");
}
// fp16 mma
__device__ __forceinline__ void mma16816h(float* d, const uint32_t* a,
                                          const uint32_t* b) {
    asm volatile("mma.sync.aligned.m16n8k16.row.col.f32.f16.f16.f32 "
                 "{%0,%1,%2,%3},{%4,%5,%6,%7},{%8,%9},{%0,%1,%2,%3};"
                 : "+f"(d[0]), "+f"(d[1]), "+f"(d[2]), "+f"(d[3])
                 : "r"(a[0]), "r"(a[1]), "r"(a[2]), "r"(a[3]),
                   "r"(b[0]), "r"(b[1]));
}

__device__ __forceinline__ float smooth_step(float u) {
    if (u <= -0.5f) return 0.0f;
    if (u >= 0.5f)  return 1.0f;
    return -2.0f * u * u * u + 1.5f * u + 0.5f;
}

// 64B-row swizzle: conflict-free ldmatrix on 64B rows
#define SWZ64R(o) ((uint32_t)(o) ^ ((((uint32_t)(o)) >> 3) & 0x30))

// ===========================================================================
// prep: repacks only (convert_x is fused into k1 now).
// ===========================================================================
#define GB ((NPAD * DDIM) / 256)          // 2048 blocks
#define GL ((ODIM * NPAD) / 256)          // 256 blocks

__global__ void prep(const float* __restrict__ nw,
                     const float* __restrict__ lw) {
    int b = blockIdx.x;
    if (b < GB) {
        int idx = b * 256 + threadIdx.x;               // over NPAD*DDIM
        int n = idx / DDIM, k = idx % DDIM;
        int t = n >> 6, i = n & 63;
        float w = 0.0f;
        if (i < NODES) w = nw[((size_t)t * DDIM + k) * NODES + i];
        g_Bt[idx] = __float2half(w);
    } else {
        int idx = (b - GB) * 256 + threadIdx.x;        // over ODIM*NPAD
        int o = idx / NPAD, k = idx % NPAD;
        int t = k >> 6, l = k & 63;
        g_LBh[idx] = __float2half(lw[((size_t)t * ODIM + o) * LEAVES + l]);
    }
}

// ===========================================================================
// K1: fused fp32->fp16 convert (pipelined +1 chunk) + fp16 mma GEMM
//     + smooth_step + tree routing -> fp16 mu.
// K chunk 32.  A32: fp32 x tiles, 3 slots, stride 36 words (conflict-free).
// A16: fp16 converted tile, DOUBLE buffered (convert(c+1) overlaps mma(c)).
// B16: fp16 W tiles (SW64), 4 slots.  ONE barrier per chunk.
// ===========================================================================
#define NCHUNK1   32
#define A32_ST    36                               // fp32 words per row
#define A32_SLOT  (128 * A32_ST * 4)               // 18432
#define A16_SLOT  (128 * 64)                       // 8192
#define B16_SLOT  (128 * 64)                       // 8192
#define A32_OFF   0
#define A16_OFF   (3 * A32_SLOT)                   // 55296
#define B16_OFF   (A16_OFF + 2 * A16_SLOT)         // 71680
#define K1_MAIN   (B16_OFF + 4 * B16_SLOT)         // 104448
#define CS_ST 133                                  // fp32 words per cs row
#define CS_BYTES (128 * CS_ST * 4)                 // 68096
#define MU_ST 136                                  // halves per mu_stage row
#define K1_EPI  (CS_BYTES + 128 * MU_ST * 2)       // 102912
#define K1_SMEM (K1_MAIN > K1_EPI ? K1_MAIN : K1_EPI)

__global__ __launch_bounds__(256, 2) void k1_tc(const float* __restrict__ x) {
    extern __shared__ char smraw[];
    const uint32_t smb = smem_u32(smraw);

    const int tid  = threadIdx.x;
    const int lane = tid & 31;
    const int wid  = tid >> 5;
    const int bn   = blockIdx.x;          // fastest: 4 bn CTAs share A rows
    const int bm   = blockIdx.y;
    const int wm   = (wid & 1) * 64;
    const int wn   = (wid >> 1) * 32;

    auto load_stage = [&](int c) {
        const uint32_t a32 = smb + A32_OFF + (c % 3) * A32_SLOT;
        const uint32_t b16 = smb + B16_OFF + (c % 4) * B16_SLOT;
        const float*  ab = x + ((size_t)bm * 128) * DDIM + c * 32;
        const __half* bb = g_Bt + ((size_t)bn * 128) * DDIM + c * 32;
        #pragma unroll
        for (int i = 0; i < 4; i++) {                 // A: 1024 x 16B units
            int u = tid + 256 * i;
            int row = u >> 3, seg = u & 7;
            cp16(a32 + (uint32_t)(row * (A32_ST * 4) + seg * 16),
                 ab + (size_t)row * DDIM + seg * 4);
        }
        #pragma unroll
        for (int i = 0; i < 2; i++) {                 // B: 512 x 16B units
            int u = tid + 256 * i;
            int row = u >> 2, seg = u & 3;
            cp16(b16 + SWZ64R(row * 64 + seg * 16),
                 bb + (size_t)row * DDIM + seg * 8);
        }
        CP_COMMIT();
    };

    auto convert = [&](int c) {        // A32[c%3] fp32 -> A16[c%2] fp16 SW64
        const uint32_t a32 = smb + A32_OFF + (c % 3) * A32_SLOT;
        const uint32_t a16 = smb + A16_OFF + (c % 2) * A16_SLOT;
        #pragma unroll
        for (int i = 0; i < 2; i++) {
            int u = tid + 256 * i;            // 512 x 16B fp16 units
            int row = u >> 2, s16 = u & 3;
            float4 f0, f1;
            lds128f(f0, a32 + (uint32_t)(row * (A32_ST * 4) + s16 * 32));
            lds128f(f1, a32 + (uint32_t)(row * (A32_ST * 4) + s16 * 32 + 16));
            __half2 h0 = __floats2half2_rn(f0.x, f0.y);
            __half2 h1 = __floats2half2_rn(f0.z, f0.w);
            __half2 h2 = __floats2half2_rn(f1.x, f1.y);
            __half2 h3 = __floats2half2_rn(f1.z, f1.w);
            sts128(a16 + SWZ64R(row * 64 + s16 * 16),
                   *(uint32_t*)&h0, *(uint32_t*)&h1,
                   *(uint32_t*)&h2, *(uint32_t*)&h3);
        }
    };

    float acc[4][4][4];
    #pragma unroll
    for (int t = 0; t < 4; t++)
        #pragma unroll
        for (int g = 0; g < 4; g++)
            #pragma unroll
            for (int e = 0; e < 4; e++) acc[t][g][e] = 0.0f;

    load_stage(0); load_stage(1); load_stage(2);
    CP_WAIT(2);
    __syncthreads();
    convert(0);

    const int a_m  = (lane & 15);
    const int a_kb = (lane >> 4) * 16;        // A k-offset bytes within k16 grp
    const int b_n  = ((lane >> 4) << 3) + (lane & 7);
    const int b_kb = ((lane >> 3) & 1) * 16;

    for (int c = 0; c < NCHUNK1; ++c) {
        if (c < NCHUNK1 - 2) { CP_WAIT(1); } else { CP_WAIT(0); }
        __syncthreads();   // publishes convert(c); mma(c-1) reads complete
        if (c + 3 < NCHUNK1) load_stage(c + 3);
        if (c + 1 < NCHUNK1) convert(c + 1);   // writes A16[(c+1)%2] (free)

        const uint32_t a16 = smb + A16_OFF + (c % 2) * A16_SLOT;
        const uint32_t b16 = smb + B16_OFF + (c % 4) * B16_SLOT;
        #pragma unroll
        for (int kk = 0; kk < 2; kk++) {
            uint32_t af[4][4];
            #pragma unroll
            for (int t = 0; t < 4; t++) {
                int m = wm + t * 16 + a_m;
                ldsm4(af[t][0], af[t][1], af[t][2], af[t][3],
                      a16 + SWZ64R(m * 64 + kk * 32 + a_kb));
            }
            uint32_t bf[2][4];
            #pragma unroll
            for (int g16 = 0; g16 < 2; g16++) {
                int n = wn + g16 * 16 + b_n;
                ldsm4(bf[g16][0], bf[g16][1], bf[g16][2], bf[g16][3],
                      b16 + SWZ64R(n * 64 + kk * 32 + b_kb));
            }
            #pragma unroll
            for (int t = 0; t < 4; t++)
                #pragma unroll
                for (int g = 0; g < 4; g++)
                    mma16816h(acc[t][g], af[t], &bf[g >> 1][(g & 1) * 2]);
        }
    }
    __syncthreads();

    // ---- stage smooth_step(s) in fp32 smem [128][CS_ST] ----
    float* cs = (float*)smraw;
    const int r0 = lane >> 2;
    const int c0 = (lane & 3) * 2;
    #pragma unroll
    for (int t = 0; t < 4; t++) {
        #pragma unroll
        for (int g = 0; g < 4; g++) {
            int m = wm + t * 16 + r0;
            int n = wn + g * 8 + c0;
            cs[m * CS_ST + n]           = smooth_step(acc[t][g][0]);
            cs[m * CS_ST + n + 1]       = smooth_step(acc[t][g][1]);
            cs[(m + 8) * CS_ST + n]     = smooth_step(acc[t][g][2]);
            cs[(m + 8) * CS_ST + n + 1] = smooth_step(acc[t][g][3]);
        }
    }
    __syncthreads();

    // ---- tree routing: depth-first walk, 6 live partials, no spills ----
    {
        __half* mu_stage = (__half*)(smraw + CS_BYTES);   // [128][MU_ST]
        const int r  = tid & 127;
        const int th = tid >> 7;                          // 0 or 1
        const float* srow = cs + r * CS_ST + th * 64;
        __half* mrow = &mu_stage[r * MU_ST + th * 64];

        const float s0 = srow[0];
        #pragma unroll
        for (int i0 = 0; i0 < 2; i0++) {
            const float p1 = i0 ? (1.0f - s0) : s0;
            const float s1 = srow[1 + i0];
            #pragma unroll
            for (int i1 = 0; i1 < 2; i1++) {
                const float p2 = p1 * (i1 ? (1.0f - s1) : s1);
                const float s2 = srow[3 + i0 * 2 + i1];
                #pragma unroll
                for (int i2 = 0; i2 < 2; i2++) {
                    const float p3 = p2 * (i2 ? (1.0f - s2) : s2);
                    const float s3 = srow[7 + i0 * 4 + i1 * 2 + i2];
                    __half hb[8];
                    #pragma unroll
                    for (int i3 = 0; i3 < 2; i3++) {
                        const float p4 = p3 * (i3 ? (1.0f - s3) : s3);
                        const float s4 = srow[15 + i0 * 8 + i1 * 4 + i2 * 2 + i3];
                        #pragma unroll
                        for (int i4 = 0; i4 < 2; i4++) {
                            const float p5 = p4 * (i4 ? (1.0f - s4) : s4);
                            const float s5 = srow[31 + i0 * 16 + i1 * 8 + i2 * 4
                                                  + i3 * 2 + i4];
                            #pragma unroll
                            for (int i5 = 0; i5 < 2; i5++) {
                                const float p6 = p5 * (i5 ? (1.0f - s5) : s5);
                                hb[i3 * 4 + i4 * 2 + i5] = __float2half(p6);
                            }
                        }
                    }
                    *(uint4*)&mrow[(i0 * 4 + i1 * 2 + i2) * 8] = *(uint4*)hb;
                }
            }
        }
    }
    __syncthreads();

    // ---- coalesced mu store: per row 128 halves = 256B contiguous ----
    {
        __half* mu_stage = (__half*)(smraw + CS_BYTES);
        const int row  = tid >> 1;
        const int half = tid & 1;
        const uint4* src = (const uint4*)&mu_stage[row * MU_ST + half * 64];
        uint4* dst = (uint4*)(g_mu + ((size_t)bm * 128 + row) * NPAD
                              + bn * 128 + half * 64);
        #pragma unroll
        for (int j = 0; j < 8; j++) dst[j] = src[j];
    }
}

// ===========================================================================
// K3: leaf GEMM, deep 6-stage K32 pipeline (unchanged from Round 13).
// out[B x 128] = mu[B x 512] * LW[128 x 512]^T
// ===========================================================================
#define K3_STAGES 6
#define NCHUNK3   16
#define K3_A_SLOT 8192
#define K3_STAGE  (2 * K3_A_SLOT)                 // 16384
#define K3_SMEM_MAIN (K3_STAGES * K3_STAGE)       // 98304
#define K3_SMEM (K3_SMEM_MAIN > (128 * 132 * 4) ? K3_SMEM_MAIN : (128 * 132 * 4))

__global__ __launch_bounds__(256, 2) void k3_leaf(float* __restrict__ out) {
    extern __shared__ char smraw[];
    const uint32_t smb = smem_u32(smraw);

    const int tid  = threadIdx.x;
    const int lane = tid & 31;
    const int wid  = tid >> 5;
    const int bm   = blockIdx.x;
    const int wm   = (wid & 1) * 64;
    const int wn   = (wid >> 1) * 32;

    auto load_stage = [&](int c) {
        const uint32_t sa = smb + (c % K3_STAGES) * K3_STAGE;
        const uint32_t sb = sa + K3_A_SLOT;
        const __half* abase = g_mu + (size_t)bm * 128 * NPAD + c * 32;
        const __half* bbase = g_LBh + c * 32;
        #pragma unroll
        for (int i = 0; i < 2; i++) {                  // A: 512 x 16B units
            int u = tid + 256 * i;
            int row = u >> 2, seg = u & 3;
            cp16(sa + SWZ64R(row * 64 + seg * 16),
                 abase + (size_t)row * NPAD + seg * 8);
        }
        #pragma unroll
        for (int i = 0; i < 2; i++) {                  // B: 512 x 16B units
            int u = tid + 256 * i;
            int row = u >> 2, seg = u & 3;
            cp16(sb + SWZ64R(row * 64 + seg * 16),
                 bbase + (size_t)row * NPAD + seg * 8);
        }
        CP_COMMIT();
    };

    float acc[4][4][4];
    #pragma unroll
    for (int t = 0; t < 4; t++)
        #pragma unroll
        for (int g = 0; g < 4; g++)
            #pragma unroll
            for (int e = 0; e < 4; e++) acc[t][g][e] = 0.0f;

    load_stage(0); load_stage(1); load_stage(2); load_stage(3); load_stage(4);

    const int a_m  = (lane & 15);
    const int a_kb = (lane >> 4) * 16;
    const int b_n  = ((lane >> 4) << 3) + (lane & 7);
    const int b_kb = ((lane >> 3) & 1) * 16;

    for (int c = 0; c < NCHUNK3; ++c) {
        if (c <= NCHUNK3 - 5)      { CP_WAIT(4); }
        else if (c == NCHUNK3 - 4) { CP_WAIT(3); }
        else if (c == NCHUNK3 - 3) { CP_WAIT(2); }
        else if (c == NCHUNK3 - 2) { CP_WAIT(1); }
        else                       { CP_WAIT(0); }
        __syncthreads();
        if (c + 5 < NCHUNK3) load_stage(c + 5);

        const uint32_t sa = smb + (c % K3_STAGES) * K3_STAGE;
        const uint32_t sb = sa + K3_A_SLOT;

        #pragma unroll
        for (int kk = 0; kk < 2; kk++) {
            uint32_t af[4][4];
            #pragma unroll
            for (int t = 0; t < 4; t++) {
                int m = wm + t * 16 + a_m;
                ldsm4(af[t][0], af[t][1], af[t][2], af[t][3],
                      sa + SWZ64R(m * 64 + kk * 32 + a_kb));
            }
            uint32_t bf[2][4];
            #pragma unroll
            for (int g16 = 0; g16 < 2; g16++) {
                int n = wn + g16 * 16 + b_n;
                ldsm4(bf[g16][0], bf[g16][1], bf[g16][2], bf[g16][3],
                      sb + SWZ64R(n * 64 + kk * 32 + b_kb));
            }
            #pragma unroll
            for (int t = 0; t < 4; t++)
                #pragma unroll
                for (int g = 0; g < 4; g++)
                    mma16816h(acc[t][g], af[t], &bf[g >> 1][(g & 1) * 2]);
        }
    }
    __syncthreads();

    float* cs = (float*)smraw;          // [128][132]
    const int r0 = lane >> 2;
    const int c0 = (lane & 3) * 2;
    #pragma unroll
    for (int t = 0; t < 4; t++) {
        #pragma unroll
        for (int g = 0; g < 4; g++) {
            int m = wm + t * 16 + r0;
            int n = wn + g * 8 + c0;
            cs[m * 132 + n]           = acc[t][g][0];
            cs[m * 132 + n + 1]       = acc[t][g][1];
            cs[(m + 8) * 132 + n]     = acc[t][g][2];
            cs[(m + 8) * 132 + n + 1] = acc[t][g][3];
        }
    }
    __syncthreads();

    {
        const int row  = tid >> 1;
        const int half = tid & 1;
        float4* dst = (float4*)(out + ((size_t)bm * 128 + row) * ODIM + half * 64);
        const float* srcr = cs + row * 132 + half * 64;
        #pragma unroll
        for (int j = 0; j < 16; j++)
            dst[j] = *(const float4*)(srcr + j * 4);
    }
}

// ===========================================================================
// Launch
// ===========================================================================
extern "C" void kernel_launch(void* const* d_in, const int* in_sizes, int n_in,
                              void* d_out, int out_size) {
    const float* x  = (const float*)d_in[0];   // [B, 1024]
    const float* nw = (const float*)d_in[1];   // [8, 1024, 63]
    const float* lw = (const float*)d_in[2];   // [8, 128, 64]
    float* out = (float*)d_out;                // [B, 128]

    int Brows = in_sizes[0] / DDIM;            // 32768

    cudaFuncSetAttribute(k1_tc,   cudaFuncAttributeMaxDynamicSharedMemorySize, K1_SMEM);
    cudaFuncSetAttribute(k3_leaf, cudaFuncAttributeMaxDynamicSharedMemorySize, K3_SMEM);

    prep   <<< GB + GL, 256 >>>(nw, lw);
    k1_tc  <<< dim3(NPAD / 128, Brows / 128), 256, K1_SMEM >>>(x);
    k3_leaf<<< Brows / 128, 256, K3_SMEM >>>(out);
}

// round 15
// speedup vs baseline: 1.0742x; 1.0742x over previous
#include <cuda_runtime.h>
#include <cuda_bf16.h>
#include <cuda_fp16.h>
#include <cstdint>

// Problem constants
#define BMAXR 32768
#define DDIM  1024
#define TTREE 8
#define NODES 63
#define LEAVES 64
#define NPAD  512
#define ODIM  128

// Scratch (static device globals -- no runtime allocation)
__device__ __align__(256) __half  g_xh[(size_t)BMAXR * DDIM];     // fp16 x
__device__ __align__(256) __half  g_Bt[(size_t)NPAD * DDIM];      // fp16 W [n][k]
__device__ __align__(256) __half  g_mu[(size_t)BMAXR * NPAD];     // fp16 mu
__device__ __align__(256) __half  g_LBh[(size_t)ODIM * NPAD];     // fp16 LW [o][k]

// ===========================================================================
// PTX helpers (all arch-generic: sm_80+ / sm_75+)
// ===========================================================================
__device__ __forceinline__ uint32_t smem_u32(const void* p) {
    uint32_t a;
    asm("{ .reg .u64 t; cvta.to.shared.u64 t, %1; cvt.u32.u64 %0, t; }"
        : "=r"(a) : "l"(p));
    return a;
}
__device__ __forceinline__ void cp16(uint32_t dst, const void* src) {
    asm volatile("cp.async.cg.shared.global [%0], [%1], 16;"
                 :: "r"(dst), "l"(src) : "memory");
}
#define CP_COMMIT() asm volatile("cp.async.commit_group;" ::: "memory")
#define CP_WAIT(n)  asm volatile("cp.async.wait_group %0;" :: "n"(n) : "memory")

__device__ __forceinline__ void ldsm4(uint32_t& r0, uint32_t& r1,
                                      uint32_t& r2, uint32_t& r3, uint32_t addr) {
    asm volatile("ldmatrix.sync.aligned.m8n8.x4.shared.b16 {%0,%1,%2,%3}, [%4];"
                 : "=r"(r0), "=r"(r1), "=r"(r2), "=r"(r3) : "r"(addr));
}
// fp16 mma
__device__ __forceinline__ void mma16816h(float* d, const uint32_t* a,
                                          const uint32_t* b) {
    asm volatile("mma.sync.aligned.m16n8k16.row.col.f32.f16.f16.f32 "
                 "{%0,%1,%2,%3},{%4,%5,%6,%7},{%8,%9},{%0,%1,%2,%3};"
                 : "+f"(d[0]), "+f"(d[1]), "+f"(d[2]), "+f"(d[3])
                 : "r"(a[0]), "r"(a[1]), "r"(a[2]), "r"(a[3]),
                   "r"(b[0]), "r"(b[1]));
}

__device__ __forceinline__ float smooth_step(float u) {
    if (u <= -0.5f) return 0.0f;
    if (u >= 0.5f)  return 1.0f;
    return -2.0f * u * u * u + 1.5f * u + 0.5f;
}

// 64B-row swizzle: conflict-free ldmatrix on 64B rows
#define SWZ64R(o) ((uint32_t)(o) ^ ((((uint32_t)(o)) >> 3) & 0x30))

// ===========================================================================
// prep: fused pre-pass (repack_b | repack_lb | convert_x), one launch.
// convert_x: 8 floats/thread (2x16B loads, 1x16B store) for full store width.
// ===========================================================================
#define GB ((NPAD * DDIM) / 256)          // 2048 blocks
#define GL ((ODIM * NPAD) / 256)          // 256 blocks
#define GX2 ((BMAXR * DDIM / 8) / 256)    // 16384 blocks

__global__ void prep(const float* __restrict__ x,
                     const float* __restrict__ nw,
                     const float* __restrict__ lw) {
    int b = blockIdx.x;
    if (b < GB) {
        int idx = b * 256 + threadIdx.x;               // over NPAD*DDIM
        int n = idx / DDIM, k = idx % DDIM;
        int t = n >> 6, i = n & 63;
        float w = 0.0f;
        if (i < NODES) w = nw[((size_t)t * DDIM + k) * NODES + i];
        g_Bt[idx] = __float2half(w);
    } else if (b < GB + GL) {
        int idx = (b - GB) * 256 + threadIdx.x;        // over ODIM*NPAD
        int o = idx / NPAD, k = idx % NPAD;
        int t = k >> 6, l = k & 63;
        g_LBh[idx] = __float2half(lw[((size_t)t * ODIM + o) * LEAVES + l]);
    } else {
        int i = (b - GB - GL) * 256 + threadIdx.x;     // over n/8 groups
        float4 v0 = ((const float4*)x)[i * 2];
        float4 v1 = ((const float4*)x)[i * 2 + 1];
        __half h[8];
        h[0] = __float2half(v0.x); h[1] = __float2half(v0.y);
        h[2] = __float2half(v0.z); h[3] = __float2half(v0.w);
        h[4] = __float2half(v1.x); h[5] = __float2half(v1.y);
        h[6] = __float2half(v1.z); h[7] = __float2half(v1.w);
        *(uint4*)&g_xh[(size_t)i * 8] = *(uint4*)h;
    }
}

// ===========================================================================
// K1: fp16 mma.sync GEMM + smooth_step + TREE ROUTING fused (Round-13 best).
// ===========================================================================
#define A_ST 72
#define A_BYTES (128 * A_ST * 2)
#define STAGE_BYTES (2 * A_BYTES)
#define K1_STAGES 3
#define NCHUNK 16
#define CS_ST 133                                 // fp32 words per cs row
#define CS_BYTES (128 * CS_ST * 4)                // 68096
#define MU_ST 136                                 // halves per mu_stage row
#define K1_SMEM (K1_STAGES * STAGE_BYTES)         // 110592

__global__ __launch_bounds__(256, 2) void k1_tc() {
    extern __shared__ char smraw[];
    const uint32_t smb = smem_u32(smraw);

    const int tid  = threadIdx.x;
    const int lane = tid & 31;
    const int wid  = tid >> 5;
    const int bn   = blockIdx.x;          // fastest: 4 bn CTAs share A rows
    const int bm   = blockIdx.y;
    const int wm   = (wid & 1) * 64;
    const int wn   = (wid >> 1) * 32;

    auto load_stage = [&](int c) {
        const int slot = c % K1_STAGES;
        const uint32_t sa = smb + slot * STAGE_BYTES;
        const uint32_t sb = sa + A_BYTES;
        const __half* abase = g_xh + (size_t)bm * 128 * DDIM + c * 64;
        const __half* bbase = g_Bt + (size_t)bn * 128 * DDIM + c * 64;
        #pragma unroll
        for (int i = 0; i < 4; i++) {
            int u = tid + 256 * i;
            int row = u >> 3, seg = u & 7;
            cp16(sa + (uint32_t)(row * A_ST + seg * 8) * 2,
                 abase + (size_t)row * DDIM + seg * 8);
        }
        #pragma unroll
        for (int i = 0; i < 4; i++) {
            int u = tid + 256 * i;
            int row = u >> 3, seg = u & 7;
            cp16(sb + (uint32_t)(row * A_ST + seg * 8) * 2,
                 bbase + (size_t)row * DDIM + seg * 8);
        }
        CP_COMMIT();
    };

    float acc[4][4][4];
    #pragma unroll
    for (int t = 0; t < 4; t++)
        #pragma unroll
        for (int g = 0; g < 4; g++)
            #pragma unroll
            for (int e = 0; e < 4; e++) acc[t][g][e] = 0.0f;

    load_stage(0);
    load_stage(1);

    const int a_m   = (lane & 15);
    const int a_k8  = (lane >> 4) * 8;
    const int b_n   = ((lane >> 4) << 3) + (lane & 7);
    const int b_k8  = ((lane >> 3) & 1) * 8;

    for (int c = 0; c < NCHUNK; ++c) {
        if (c == NCHUNK - 1) { CP_WAIT(0); } else { CP_WAIT(1); }
        __syncthreads();
        if (c + 2 < NCHUNK) load_stage(c + 2);

        const int slot = c % K1_STAGES;
        const uint32_t sa = smb + slot * STAGE_BYTES;
        const uint32_t sb = sa + A_BYTES;

        #pragma unroll
        for (int kk = 0; kk < 4; kk++) {
            uint32_t af[4][4];
            #pragma unroll
            for (int t = 0; t < 4; t++) {
                int m = wm + t * 16 + a_m;
                ldsm4(af[t][0], af[t][1], af[t][2], af[t][3],
                      sa + (uint32_t)(m * A_ST + kk * 16 + a_k8) * 2);
            }
            uint32_t bf[2][4];
            #pragma unroll
            for (int g16 = 0; g16 < 2; g16++) {
                int n = wn + g16 * 16 + b_n;
                ldsm4(bf[g16][0], bf[g16][1], bf[g16][2], bf[g16][3],
                      sb + (uint32_t)(n * A_ST + kk * 16 + b_k8) * 2);
            }
            #pragma unroll
            for (int t = 0; t < 4; t++)
                #pragma unroll
                for (int g = 0; g < 4; g++)
                    mma16816h(acc[t][g], af[t], &bf[g >> 1][(g & 1) * 2]);
        }
    }
    __syncthreads();

    // ---- stage smooth_step(s) in fp32 smem [128][CS_ST] ----
    float* cs = (float*)smraw;
    const int r0 = lane >> 2;
    const int c0 = (lane & 3) * 2;
    #pragma unroll
    for (int t = 0; t < 4; t++) {
        #pragma unroll
        for (int g = 0; g < 4; g++) {
            int m = wm + t * 16 + r0;
            int n = wn + g * 8 + c0;
            cs[m * CS_ST + n]           = smooth_step(acc[t][g][0]);
            cs[m * CS_ST + n + 1]       = smooth_step(acc[t][g][1]);
            cs[(m + 8) * CS_ST + n]     = smooth_step(acc[t][g][2]);
            cs[(m + 8) * CS_ST + n + 1] = smooth_step(acc[t][g][3]);
        }
    }
    __syncthreads();

    // ---- tree routing: depth-first walk, 6 live partials, no spills ----
    {
        __half* mu_stage = (__half*)(smraw + CS_BYTES);   // [128][MU_ST]
        const int r  = tid & 127;
        const int th = tid >> 7;                          // 0 or 1
        const float* srow = cs + r * CS_ST + th * 64;
        __half* mrow = &mu_stage[r * MU_ST + th * 64];

        const float s0 = srow[0];
        #pragma unroll
        for (int i0 = 0; i0 < 2; i0++) {
            const float p1 = i0 ? (1.0f - s0) : s0;
            const float s1 = srow[1 + i0];
            #pragma unroll
            for (int i1 = 0; i1 < 2; i1++) {
                const float p2 = p1 * (i1 ? (1.0f - s1) : s1);
                const float s2 = srow[3 + i0 * 2 + i1];
                #pragma unroll
                for (int i2 = 0; i2 < 2; i2++) {
                    const float p3 = p2 * (i2 ? (1.0f - s2) : s2);
                    const float s3 = srow[7 + i0 * 4 + i1 * 2 + i2];
                    __half hb[8];
                    #pragma unroll
                    for (int i3 = 0; i3 < 2; i3++) {
                        const float p4 = p3 * (i3 ? (1.0f - s3) : s3);
                        const float s4 = srow[15 + i0 * 8 + i1 * 4 + i2 * 2 + i3];
                        #pragma unroll
                        for (int i4 = 0; i4 < 2; i4++) {
                            const float p5 = p4 * (i4 ? (1.0f - s4) : s4);
                            const float s5 = srow[31 + i0 * 16 + i1 * 8 + i2 * 4
                                                  + i3 * 2 + i4];
                            #pragma unroll
                            for (int i5 = 0; i5 < 2; i5++) {
                                const float p6 = p5 * (i5 ? (1.0f - s5) : s5);
                                hb[i3 * 4 + i4 * 2 + i5] = __float2half(p6);
                            }
                        }
                    }
                    *(uint4*)&mrow[(i0 * 4 + i1 * 2 + i2) * 8] = *(uint4*)hb;
                }
            }
        }
    }
    __syncthreads();

    // ---- coalesced mu store: per row 128 halves = 256B contiguous ----
    {
        __half* mu_stage = (__half*)(smraw + CS_BYTES);
        const int row  = tid >> 1;
        const int half = tid & 1;
        const uint4* src = (const uint4*)&mu_stage[row * MU_ST + half * 64];
        uint4* dst = (uint4*)(g_mu + ((size_t)bm * 128 + row) * NPAD
                              + bn * 128 + half * 64);
        #pragma unroll
        for (int j = 0; j < 8; j++) dst[j] = src[j];
    }
}

// ===========================================================================
// K3: leaf GEMM, deep 6-stage K32 pipeline (Round-13 version).
// out[B x 128] = mu[B x 512] * LW[128 x 512]^T
// ===========================================================================
#define K3_STAGES 6
#define NCHUNK3   16
#define K3_A_SLOT 8192
#define K3_STAGE  (2 * K3_A_SLOT)                 // 16384
#define K3_SMEM_MAIN (K3_STAGES * K3_STAGE)       // 98304
#define K3_SMEM (K3_SMEM_MAIN > (128 * 132 * 4) ? K3_SMEM_MAIN : (128 * 132 * 4))

__global__ __launch_bounds__(256, 2) void k3_leaf(float* __restrict__ out) {
    extern __shared__ char smraw[];
    const uint32_t smb = smem_u32(smraw);

    const int tid  = threadIdx.x;
    const int lane = tid & 31;
    const int wid  = tid >> 5;
    const int bm   = blockIdx.x;
    const int wm   = (wid & 1) * 64;
    const int wn   = (wid >> 1) * 32;

    auto load_stage = [&](int c) {
        const uint32_t sa = smb + (c % K3_STAGES) * K3_STAGE;
        const uint32_t sb = sa + K3_A_SLOT;
        const __half* abase = g_mu + (size_t)bm * 128 * NPAD + c * 32;
        const __half* bbase = g_LBh + c * 32;
        #pragma unroll
        for (int i = 0; i < 2; i++) {                  // A: 512 x 16B units
            int u = tid + 256 * i;
            int row = u >> 2, seg = u & 3;
            cp16(sa + SWZ64R(row * 64 + seg * 16),
                 abase + (size_t)row * NPAD + seg * 8);
        }
        #pragma unroll
        for (int i = 0; i < 2; i++) {                  // B: 512 x 16B units
            int u = tid + 256 * i;
            int row = u >> 2, seg = u & 3;
            cp16(sb + SWZ64R(row * 64 + seg * 16),
                 bbase + (size_t)row * NPAD + seg * 8);
        }
        CP_COMMIT();
    };

    float acc[4][4][4];
    #pragma unroll
    for (int t = 0; t < 4; t++)
        #pragma unroll
        for (int g = 0; g < 4; g++)
            #pragma unroll
            for (int e = 0; e < 4; e++) acc[t][g][e] = 0.0f;

    load_stage(0); load_stage(1); load_stage(2); load_stage(3); load_stage(4);

    const int a_m  = (lane & 15);
    const int a_kb = (lane >> 4) * 16;
    const int b_n  = ((lane >> 4) << 3) + (lane & 7);
    const int b_kb = ((lane >> 3) & 1) * 16;

    for (int c = 0; c < NCHUNK3; ++c) {
        if (c <= NCHUNK3 - 5)      { CP_WAIT(4); }
        else if (c == NCHUNK3 - 4) { CP_WAIT(3); }
        else if (c == NCHUNK3 - 3) { CP_WAIT(2); }
        else if (c == NCHUNK3 - 2) { CP_WAIT(1); }
        else                       { CP_WAIT(0); }
        __syncthreads();
        if (c + 5 < NCHUNK3) load_stage(c + 5);

        const uint32_t sa = smb + (c % K3_STAGES) * K3_STAGE;
        const uint32_t sb = sa + K3_A_SLOT;

        #pragma unroll
        for (int kk = 0; kk < 2; kk++) {
            uint32_t af[4][4];
            #pragma unroll
            for (int t = 0; t < 4; t++) {
                int m = wm + t * 16 + a_m;
                ldsm4(af[t][0], af[t][1], af[t][2], af[t][3],
                      sa + SWZ64R(m * 64 + kk * 32 + a_kb));
            }
            uint32_t bf[2][4];
            #pragma unroll
            for (int g16 = 0; g16 < 2; g16++) {
                int n = wn + g16 * 16 + b_n;
                ldsm4(bf[g16][0], bf[g16][1], bf[g16][2], bf[g16][3],
                      sb + SWZ64R(n * 64 + kk * 32 + b_kb));
            }
            #pragma unroll
            for (int t = 0; t < 4; t++)
                #pragma unroll
                for (int g = 0; g < 4; g++)
                    mma16816h(acc[t][g], af[t], &bf[g >> 1][(g & 1) * 2]);
        }
    }
    __syncthreads();

    float* cs = (float*)smraw;          // [128][132]
    const int r0 = lane >> 2;
    const int c0 = (lane & 3) * 2;
    #pragma unroll
    for (int t = 0; t < 4; t++) {
        #pragma unroll
        for (int g = 0; g < 4; g++) {
            int m = wm + t * 16 + r0;
            int n = wn + g * 8 + c0;
            cs[m * 132 + n]           = acc[t][g][0];
            cs[m * 132 + n + 1]       = acc[t][g][1];
            cs[(m + 8) * 132 + n]     = acc[t][g][2];
            cs[(m + 8) * 132 + n + 1] = acc[t][g][3];
        }
    }
    __syncthreads();

    {
        const int row  = tid >> 1;
        const int half = tid & 1;
        float4* dst = (float4*)(out + ((size_t)bm * 128 + row) * ODIM + half * 64);
        const float* srcr = cs + row * 132 + half * 64;
        #pragma unroll
        for (int j = 0; j < 16; j++)
            dst[j] = *(const float4*)(srcr + j * 4);
    }
}

// ===========================================================================
// Launch
// ===========================================================================
extern "C" void kernel_launch(void* const* d_in, const int* in_sizes, int n_in,
                              void* d_out, int out_size) {
    const float* x  = (const float*)d_in[0];   // [B, 1024]
    const float* nw = (const float*)d_in[1];   // [8, 1024, 63]
    const float* lw = (const float*)d_in[2];   // [8, 128, 64]
    float* out = (float*)d_out;                // [B, 128]

    int Brows = in_sizes[0] / DDIM;            // 32768

    cudaFuncSetAttribute(k1_tc,   cudaFuncAttributeMaxDynamicSharedMemorySize, K1_SMEM);
    cudaFuncSetAttribute(k3_leaf, cudaFuncAttributeMaxDynamicSharedMemorySize, K3_SMEM);

    prep   <<< GB + GL + GX2, 256 >>>(x, nw, lw);
    k1_tc  <<< dim3(NPAD / 128, Brows / 128), 256, K1_SMEM >>>();
    k3_leaf<<< Brows / 128, 256, K3_SMEM >>>(out);
}

// round 16
// speedup vs baseline: 1.0906x; 1.0152x over previous
#include <cuda_runtime.h>
#include <cuda_bf16.h>
#include <cuda_fp16.h>
#include <cstdint>

// Problem constants
#define BMAXR 32768
#define DDIM  1024
#define TTREE 8
#define NODES 63
#define LEAVES 64
#define NPAD  512
#define ODIM  128

// Scratch (static device globals -- no runtime allocation)
__device__ __align__(256) __half  g_xh[(size_t)BMAXR * DDIM];     // fp16 x
__device__ __align__(256) __half  g_Bt[(size_t)NPAD * DDIM];      // fp16 W [n][k]
__device__ __align__(256) __half  g_mu[(size_t)BMAXR * NPAD];     // fp16 mu
__device__ __align__(256) __half  g_LBh[(size_t)ODIM * NPAD];     // fp16 LW [o][k]

// ===========================================================================
// PTX helpers (all arch-generic: sm_80+ / sm_75+)
// ===========================================================================
__device__ __forceinline__ uint32_t smem_u32(const void* p) {
    uint32_t a;
    asm("{ .reg .u64 t; cvta.to.shared.u64 t, %1; cvt.u32.u64 %0, t; }"
        : "=r"(a) : "l"(p));
    return a;
}
__device__ __forceinline__ void cp16(uint32_t dst, const void* src) {
    asm volatile("cp.async.cg.shared.global [%0], [%1], 16;"
                 :: "r"(dst), "l"(src) : "memory");
}
#define CP_COMMIT() asm volatile("cp.async.commit_group;" ::: "memory")
#define CP_WAIT(n)  asm volatile("cp.async.wait_group %0;" :: "n"(n) : "memory")

__device__ __forceinline__ void ldsm4(uint32_t& r0, uint32_t& r1,
                                      uint32_t& r2, uint32_t& r3, uint32_t addr) {
    asm volatile("ldmatrix.sync.aligned.m8n8.x4.shared.b16 {%0,%1,%2,%3}, [%4];"
                 : "=r"(r0), "=r"(r1), "=r"(r2), "=r"(r3) : "r"(addr));
}
// fp16 mma
__device__ __forceinline__ void mma16816h(float* d, const uint32_t* a,
                                          const uint32_t* b) {
    asm volatile("mma.sync.aligned.m16n8k16.row.col.f32.f16.f16.f32 "
                 "{%0,%1,%2,%3},{%4,%5,%6,%7},{%8,%9},{%0,%1,%2,%3};"
                 : "+f"(d[0]), "+f"(d[1]), "+f"(d[2]), "+f"(d[3])
                 : "r"(a[0]), "r"(a[1]), "r"(a[2]), "r"(a[3]),
                   "r"(b[0]), "r"(b[1]));
}

__device__ __forceinline__ float smooth_step(float u) {
    if (u <= -0.5f) return 0.0f;
    if (u >= 0.5f)  return 1.0f;
    return -2.0f * u * u * u + 1.5f * u + 0.5f;
}

// 64B-row swizzle: conflict-free ldmatrix on 64B rows
#define SWZ64R(o) ((uint32_t)(o) ^ ((((uint32_t)(o)) >> 3) & 0x30))

// ===========================================================================
// prep: fused pre-pass (repack_b | repack_lb | convert_x), one launch.
// convert_x: 8 floats/thread (2x16B loads, 1x16B store) for full store width.
// ===========================================================================
#define GB ((NPAD * DDIM) / 256)          // 2048 blocks
#define GL ((ODIM * NPAD) / 256)          // 256 blocks
#define GX2 ((BMAXR * DDIM / 8) / 256)    // 16384 blocks

__global__ void prep(const float* __restrict__ x,
                     const float* __restrict__ nw,
                     const float* __restrict__ lw) {
    int b = blockIdx.x;
    if (b < GB) {
        int idx = b * 256 + threadIdx.x;               // over NPAD*DDIM
        int n = idx / DDIM, k = idx % DDIM;
        int t = n >> 6, i = n & 63;
        float w = 0.0f;
        if (i < NODES) w = nw[((size_t)t * DDIM + k) * NODES + i];
        g_Bt[idx] = __float2half(w);
    } else if (b < GB + GL) {
        int idx = (b - GB) * 256 + threadIdx.x;        // over ODIM*NPAD
        int o = idx / NPAD, k = idx % NPAD;
        int t = k >> 6, l = k & 63;
        g_LBh[idx] = __float2half(lw[((size_t)t * ODIM + o) * LEAVES + l]);
    } else {
        int i = (b - GB - GL) * 256 + threadIdx.x;     // over n/8 groups
        float4 v0 = ((const float4*)x)[i * 2];
        float4 v1 = ((const float4*)x)[i * 2 + 1];
        __half h[8];
        h[0] = __float2half(v0.x); h[1] = __float2half(v0.y);
        h[2] = __float2half(v0.z); h[3] = __float2half(v0.w);
        h[4] = __float2half(v1.x); h[5] = __float2half(v1.y);
        h[6] = __float2half(v1.z); h[7] = __float2half(v1.w);
        *(uint4*)&g_xh[(size_t)i * 8] = *(uint4*)h;
    }
}

// ===========================================================================
// K1: fp16 mma.sync GEMM + smooth_step + TREE ROUTING fused.
// Mainloop restructured to k3's proven deep pipeline: K-chunk 32, 6 stages
// (16 KB/stage, SW64R swizzle), prefetch depth 5 -> smoother tensor feed.
// ===========================================================================
#define K1_STAGES 6
#define NCHUNK1   32
#define K1_A_SLOT 8192                             // 128 x 32 fp16 (64B rows)
#define K1_STAGE  (2 * K1_A_SLOT)                  // 16384
#define K1_MAIN   (K1_STAGES * K1_STAGE)           // 98304
#define CS_ST 133                                  // fp32 words per cs row
#define CS_BYTES (128 * CS_ST * 4)                 // 68096
#define MU_ST 136                                  // halves per mu_stage row
#define K1_EPI  (CS_BYTES + 128 * MU_ST * 2)       // 102912
#define K1_SMEM (K1_MAIN > K1_EPI ? K1_MAIN : K1_EPI)

__global__ __launch_bounds__(256, 2) void k1_tc() {
    extern __shared__ char smraw[];
    const uint32_t smb = smem_u32(smraw);

    const int tid  = threadIdx.x;
    const int lane = tid & 31;
    const int wid  = tid >> 5;
    const int bn   = blockIdx.x;          // fastest: 4 bn CTAs share A rows
    const int bm   = blockIdx.y;
    const int wm   = (wid & 1) * 64;
    const int wn   = (wid >> 1) * 32;

    auto load_stage = [&](int c) {
        const uint32_t sa = smb + (c % K1_STAGES) * K1_STAGE;
        const uint32_t sb = sa + K1_A_SLOT;
        const __half* abase = g_xh + (size_t)bm * 128 * DDIM + c * 32;
        const __half* bbase = g_Bt + (size_t)bn * 128 * DDIM + c * 32;
        #pragma unroll
        for (int i = 0; i < 2; i++) {                  // A: 512 x 16B units
            int u = tid + 256 * i;
            int row = u >> 2, seg = u & 3;
            cp16(sa + SWZ64R(row * 64 + seg * 16),
                 abase + (size_t)row * DDIM + seg * 8);
        }
        #pragma unroll
        for (int i = 0; i < 2; i++) {                  // B: 512 x 16B units
            int u = tid + 256 * i;
            int row = u >> 2, seg = u & 3;
            cp16(sb + SWZ64R(row * 64 + seg * 16),
                 bbase + (size_t)row * DDIM + seg * 8);
        }
        CP_COMMIT();
    };

    float acc[4][4][4];
    #pragma unroll
    for (int t = 0; t < 4; t++)
        #pragma unroll
        for (int g = 0; g < 4; g++)
            #pragma unroll
            for (int e = 0; e < 4; e++) acc[t][g][e] = 0.0f;

    load_stage(0); load_stage(1); load_stage(2); load_stage(3); load_stage(4);

    const int a_m  = (lane & 15);
    const int a_kb = (lane >> 4) * 16;        // bytes within 32B k16 group
    const int b_n  = ((lane >> 4) << 3) + (lane & 7);
    const int b_kb = ((lane >> 3) & 1) * 16;

    for (int c = 0; c < NCHUNK1; ++c) {
        if (c <= NCHUNK1 - 5)      { CP_WAIT(4); }
        else if (c == NCHUNK1 - 4) { CP_WAIT(3); }
        else if (c == NCHUNK1 - 3) { CP_WAIT(2); }
        else if (c == NCHUNK1 - 2) { CP_WAIT(1); }
        else                       { CP_WAIT(0); }
        __syncthreads();
        if (c + 5 < NCHUNK1) load_stage(c + 5);

        const uint32_t sa = smb + (c % K1_STAGES) * K1_STAGE;
        const uint32_t sb = sa + K1_A_SLOT;

        #pragma unroll
        for (int kk = 0; kk < 2; kk++) {
            uint32_t af[4][4];
            #pragma unroll
            for (int t = 0; t < 4; t++) {
                int m = wm + t * 16 + a_m;
                ldsm4(af[t][0], af[t][1], af[t][2], af[t][3],
                      sa + SWZ64R(m * 64 + kk * 32 + a_kb));
            }
            uint32_t bf[2][4];
            #pragma unroll
            for (int g16 = 0; g16 < 2; g16++) {
                int n = wn + g16 * 16 + b_n;
                ldsm4(bf[g16][0], bf[g16][1], bf[g16][2], bf[g16][3],
                      sb + SWZ64R(n * 64 + kk * 32 + b_kb));
            }
            #pragma unroll
            for (int t = 0; t < 4; t++)
                #pragma unroll
                for (int g = 0; g < 4; g++)
                    mma16816h(acc[t][g], af[t], &bf[g >> 1][(g & 1) * 2]);
        }
    }
    __syncthreads();

    // ---- stage smooth_step(s) in fp32 smem [128][CS_ST] ----
    float* cs = (float*)smraw;
    const int r0 = lane >> 2;
    const int c0 = (lane & 3) * 2;
    #pragma unroll
    for (int t = 0; t < 4; t++) {
        #pragma unroll
        for (int g = 0; g < 4; g++) {
            int m = wm + t * 16 + r0;
            int n = wn + g * 8 + c0;
            cs[m * CS_ST + n]           = smooth_step(acc[t][g][0]);
            cs[m * CS_ST + n + 1]       = smooth_step(acc[t][g][1]);
            cs[(m + 8) * CS_ST + n]     = smooth_step(acc[t][g][2]);
            cs[(m + 8) * CS_ST + n + 1] = smooth_step(acc[t][g][3]);
        }
    }
    __syncthreads();

    // ---- tree routing: depth-first walk, 6 live partials, no spills ----
    {
        __half* mu_stage = (__half*)(smraw + CS_BYTES);   // [128][MU_ST]
        const int r  = tid & 127;
        const int th = tid >> 7;                          // 0 or 1
        const float* srow = cs + r * CS_ST + th * 64;
        __half* mrow = &mu_stage[r * MU_ST + th * 64];

        const float s0 = srow[0];
        #pragma unroll
        for (int i0 = 0; i0 < 2; i0++) {
            const float p1 = i0 ? (1.0f - s0) : s0;
            const float s1 = srow[1 + i0];
            #pragma unroll
            for (int i1 = 0; i1 < 2; i1++) {
                const float p2 = p1 * (i1 ? (1.0f - s1) : s1);
                const float s2 = srow[3 + i0 * 2 + i1];
                #pragma unroll
                for (int i2 = 0; i2 < 2; i2++) {
                    const float p3 = p2 * (i2 ? (1.0f - s2) : s2);
                    const float s3 = srow[7 + i0 * 4 + i1 * 2 + i2];
                    __half hb[8];
                    #pragma unroll
                    for (int i3 = 0; i3 < 2; i3++) {
                        const float p4 = p3 * (i3 ? (1.0f - s3) : s3);
                        const float s4 = srow[15 + i0 * 8 + i1 * 4 + i2 * 2 + i3];
                        #pragma unroll
                        for (int i4 = 0; i4 < 2; i4++) {
                            const float p5 = p4 * (i4 ? (1.0f - s4) : s4);
                            const float s5 = srow[31 + i0 * 16 + i1 * 8 + i2 * 4
                                                  + i3 * 2 + i4];
                            #pragma unroll
                            for (int i5 = 0; i5 < 2; i5++) {
                                const float p6 = p5 * (i5 ? (1.0f - s5) : s5);
                                hb[i3 * 4 + i4 * 2 + i5] = __float2half(p6);
                            }
                        }
                    }
                    *(uint4*)&mrow[(i0 * 4 + i1 * 2 + i2) * 8] = *(uint4*)hb;
                }
            }
        }
    }
    __syncthreads();

    // ---- coalesced mu store: per row 128 halves = 256B contiguous ----
    {
        __half* mu_stage = (__half*)(smraw + CS_BYTES);
        const int row  = tid >> 1;
        const int half = tid & 1;
        const uint4* src = (const uint4*)&mu_stage[row * MU_ST + half * 64];
        uint4* dst = (uint4*)(g_mu + ((size_t)bm * 128 + row) * NPAD
                              + bn * 128 + half * 64);
        #pragma unroll
        for (int j = 0; j < 8; j++) dst[j] = src[j];
    }
}

// ===========================================================================
// K3: leaf GEMM, deep 6-stage K32 pipeline (unchanged).
// out[B x 128] = mu[B x 512] * LW[128 x 512]^T
// ===========================================================================
#define K3_STAGES 6
#define NCHUNK3   16
#define K3_A_SLOT 8192
#define K3_STAGE  (2 * K3_A_SLOT)                 // 16384
#define K3_SMEM_MAIN (K3_STAGES * K3_STAGE)       // 98304
#define K3_SMEM (K3_SMEM_MAIN > (128 * 132 * 4) ? K3_SMEM_MAIN : (128 * 132 * 4))

__global__ __launch_bounds__(256, 2) void k3_leaf(float* __restrict__ out) {
    extern __shared__ char smraw[];
    const uint32_t smb = smem_u32(smraw);

    const int tid  = threadIdx.x;
    const int lane = tid & 31;
    const int wid  = tid >> 5;
    const int bm   = blockIdx.x;
    const int wm   = (wid & 1) * 64;
    const int wn   = (wid >> 1) * 32;

    auto load_stage = [&](int c) {
        const uint32_t sa = smb + (c % K3_STAGES) * K3_STAGE;
        const uint32_t sb = sa + K3_A_SLOT;
        const __half* abase = g_mu + (size_t)bm * 128 * NPAD + c * 32;
        const __half* bbase = g_LBh + c * 32;
        #pragma unroll
        for (int i = 0; i < 2; i++) {                  // A: 512 x 16B units
            int u = tid + 256 * i;
            int row = u >> 2, seg = u & 3;
            cp16(sa + SWZ64R(row * 64 + seg * 16),
                 abase + (size_t)row * NPAD + seg * 8);
        }
        #pragma unroll
        for (int i = 0; i < 2; i++) {                  // B: 512 x 16B units
            int u = tid + 256 * i;
            int row = u >> 2, seg = u & 3;
            cp16(sb + SWZ64R(row * 64 + seg * 16),
                 bbase + (size_t)row * NPAD + seg * 8);
        }
        CP_COMMIT();
    };

    float acc[4][4][4];
    #pragma unroll
    for (int t = 0; t < 4; t++)
        #pragma unroll
        for (int g = 0; g < 4; g++)
            #pragma unroll
            for (int e = 0; e < 4; e++) acc[t][g][e] = 0.0f;

    load_stage(0); load_stage(1); load_stage(2); load_stage(3); load_stage(4);

    const int a_m  = (lane & 15);
    const int a_kb = (lane >> 4) * 16;
    const int b_n  = ((lane >> 4) << 3) + (lane & 7);
    const int b_kb = ((lane >> 3) & 1) * 16;

    for (int c = 0; c < NCHUNK3; ++c) {
        if (c <= NCHUNK3 - 5)      { CP_WAIT(4); }
        else if (c == NCHUNK3 - 4) { CP_WAIT(3); }
        else if (c == NCHUNK3 - 3) { CP_WAIT(2); }
        else if (c == NCHUNK3 - 2) { CP_WAIT(1); }
        else                       { CP_WAIT(0); }
        __syncthreads();
        if (c + 5 < NCHUNK3) load_stage(c + 5);

        const uint32_t sa = smb + (c % K3_STAGES) * K3_STAGE;
        const uint32_t sb = sa + K3_A_SLOT;

        #pragma unroll
        for (int kk = 0; kk < 2; kk++) {
            uint32_t af[4][4];
            #pragma unroll
            for (int t = 0; t < 4; t++) {
                int m = wm + t * 16 + a_m;
                ldsm4(af[t][0], af[t][1], af[t][2], af[t][3],
                      sa + SWZ64R(m * 64 + kk * 32 + a_kb));
            }
            uint32_t bf[2][4];
            #pragma unroll
            for (int g16 = 0; g16 < 2; g16++) {
                int n = wn + g16 * 16 + b_n;
                ldsm4(bf[g16][0], bf[g16][1], bf[g16][2], bf[g16][3],
                      sb + SWZ64R(n * 64 + kk * 32 + b_kb));
            }
            #pragma unroll
            for (int t = 0; t < 4; t++)
                #pragma unroll
                for (int g = 0; g < 4; g++)
                    mma16816h(acc[t][g], af[t], &bf[g >> 1][(g & 1) * 2]);
        }
    }
    __syncthreads();

    float* cs = (float*)smraw;          // [128][132]
    const int r0 = lane >> 2;
    const int c0 = (lane & 3) * 2;
    #pragma unroll
    for (int t = 0; t < 4; t++) {
        #pragma unroll
        for (int g = 0; g < 4; g++) {
            int m = wm + t * 16 + r0;
            int n = wn + g * 8 + c0;
            cs[m * 132 + n]           = acc[t][g][0];
            cs[m * 132 + n + 1]       = acc[t][g][1];
            cs[(m + 8) * 132 + n]     = acc[t][g][2];
            cs[(m + 8) * 132 + n + 1] = acc[t][g][3];
        }
    }
    __syncthreads();

    {
        const int row  = tid >> 1;
        const int half = tid & 1;
        float4* dst = (float4*)(out + ((size_t)bm * 128 + row) * ODIM + half * 64);
        const float* srcr = cs + row * 132 + half * 64;
        #pragma unroll
        for (int j = 0; j < 16; j++)
            dst[j] = *(const float4*)(srcr + j * 4);
    }
}

// ===========================================================================
// Launch
// ===========================================================================
extern "C" void kernel_launch(void* const* d_in, const int* in_sizes, int n_in,
                              void* d_out, int out_size) {
    const float* x  = (const float*)d_in[0];   // [B, 1024]
    const float* nw = (const float*)d_in[1];   // [8, 1024, 63]
    const float* lw = (const float*)d_in[2];   // [8, 128, 64]
    float* out = (float*)d_out;                // [B, 128]

    int Brows = in_sizes[0] / DDIM;            // 32768

    cudaFuncSetAttribute(k1_tc,   cudaFuncAttributeMaxDynamicSharedMemorySize, K1_SMEM);
    cudaFuncSetAttribute(k3_leaf, cudaFuncAttributeMaxDynamicSharedMemorySize, K3_SMEM);

    prep   <<< GB + GL + GX2, 256 >>>(x, nw, lw);
    k1_tc  <<< dim3(NPAD / 128, Brows / 128), 256, K1_SMEM >>>();
    k3_leaf<<< Brows / 128, 256, K3_SMEM >>>(out);
}

// round 17
// speedup vs baseline: 1.1031x; 1.0115x over previous
#include <cuda_runtime.h>
#include <cuda_bf16.h>
#include <cuda_fp16.h>
#include <cstdint>

// Problem constants
#define BMAXR 32768
#define DDIM  1024
#define TTREE 8
#define NODES 63
#define LEAVES 64
#define NPAD  512
#define ODIM  128

// Scratch (static device globals -- no runtime allocation)
__device__ __align__(256) __half  g_xh[(size_t)BMAXR * DDIM];     // fp16 x
__device__ __align__(256) __half  g_Bt[(size_t)NPAD * DDIM];      // fp16 W [n][k]
__device__ __align__(256) __half  g_mu[(size_t)BMAXR * NPAD];     // fp16 mu
__device__ __align__(256) __half  g_LBh[(size_t)ODIM * NPAD];     // fp16 LW [o][k]

// ===========================================================================
// PTX helpers (all arch-generic: sm_80+ / sm_75+)
// ===========================================================================
__device__ __forceinline__ uint32_t smem_u32(const void* p) {
    uint32_t a;
    asm("{ .reg .u64 t; cvta.to.shared.u64 t, %1; cvt.u32.u64 %0, t; }"
        : "=r"(a) : "l"(p));
    return a;
}
__device__ __forceinline__ void cp16(uint32_t dst, const void* src) {
    asm volatile("cp.async.cg.shared.global [%0], [%1], 16;"
                 :: "r"(dst), "l"(src) : "memory");
}
#define CP_COMMIT() asm volatile("cp.async.commit_group;" ::: "memory")
#define CP_WAIT(n)  asm volatile("cp.async.wait_group %0;" :: "n"(n) : "memory")

__device__ __forceinline__ void ldsm4(uint32_t& r0, uint32_t& r1,
                                      uint32_t& r2, uint32_t& r3, uint32_t addr) {
    asm volatile("ldmatrix.sync.aligned.m8n8.x4.shared.b16 {%0,%1,%2,%3}, [%4];"
                 : "=r"(r0), "=r"(r1), "=r"(r2), "=r"(r3) : "r"(addr));
}
// fp16 mma
__device__ __forceinline__ void mma16816h(float* d, const uint32_t* a,
                                          const uint32_t* b) {
    asm volatile("mma.sync.aligned.m16n8k16.row.col.f32.f16.f16.f32 "
                 "{%0,%1,%2,%3},{%4,%5,%6,%7},{%8,%9},{%0,%1,%2,%3};"
                 : "+f"(d[0]), "+f"(d[1]), "+f"(d[2]), "+f"(d[3])
                 : "r"(a[0]), "r"(a[1]), "r"(a[2]), "r"(a[3]),
                   "r"(b[0]), "r"(b[1]));
}

__device__ __forceinline__ float smooth_step(float u) {
    if (u <= -0.5f) return 0.0f;
    if (u >= 0.5f)  return 1.0f;
    return -2.0f * u * u * u + 1.5f * u + 0.5f;
}

// 64B-row swizzle: conflict-free ldmatrix on 64B rows
#define SWZ64R(o) ((uint32_t)(o) ^ ((((uint32_t)(o)) >> 3) & 0x30))

// ===========================================================================
// prep: fused pre-pass (repack_b | repack_lb | convert_x), one launch.
// ===========================================================================
#define GB ((NPAD * DDIM) / 256)          // 2048 blocks
#define GL ((ODIM * NPAD) / 256)          // 256 blocks
#define GX2 ((BMAXR * DDIM / 8) / 256)    // 16384 blocks

__global__ void prep(const float* __restrict__ x,
                     const float* __restrict__ nw,
                     const float* __restrict__ lw) {
    int b = blockIdx.x;
    if (b < GB) {
        int idx = b * 256 + threadIdx.x;               // over NPAD*DDIM
        int n = idx / DDIM, k = idx % DDIM;
        int t = n >> 6, i = n & 63;
        float w = 0.0f;
        if (i < NODES) w = nw[((size_t)t * DDIM + k) * NODES + i];
        g_Bt[idx] = __float2half(w);
    } else if (b < GB + GL) {
        int idx = (b - GB) * 256 + threadIdx.x;        // over ODIM*NPAD
        int o = idx / NPAD, k = idx % NPAD;
        int t = k >> 6, l = k & 63;
        g_LBh[idx] = __float2half(lw[((size_t)t * ODIM + o) * LEAVES + l]);
    } else {
        int i = (b - GB - GL) * 256 + threadIdx.x;     // over n/8 groups
        float4 v0 = ((const float4*)x)[i * 2];
        float4 v1 = ((const float4*)x)[i * 2 + 1];
        __half h[8];
        h[0] = __float2half(v0.x); h[1] = __float2half(v0.y);
        h[2] = __float2half(v0.z); h[3] = __float2half(v0.w);
        h[4] = __float2half(v1.x); h[5] = __float2half(v1.y);
        h[6] = __float2half(v1.z); h[7] = __float2half(v1.w);
        *(uint4*)&g_xh[(size_t)i * 8] = *(uint4*)h;
    }
}

// ===========================================================================
// K1: fp16 mma.sync GEMM + smooth_step + TREE ROUTING fused.
// K-chunk 32, 6 stages (16 KB/stage, SW64R), prefetch depth 5.  (R16 best.)
// ===========================================================================
#define K1_STAGES 6
#define NCHUNK1   32
#define K1_A_SLOT 8192                             // 128 x 32 fp16 (64B rows)
#define K1_STAGE  (2 * K1_A_SLOT)                  // 16384
#define K1_MAIN   (K1_STAGES * K1_STAGE)           // 98304
#define CS_ST 133                                  // fp32 words per cs row
#define CS_BYTES (128 * CS_ST * 4)                 // 68096
#define MU_ST 136                                  // halves per mu_stage row
#define K1_EPI  (CS_BYTES + 128 * MU_ST * 2)       // 102912
#define K1_SMEM (K1_MAIN > K1_EPI ? K1_MAIN : K1_EPI)

__global__ __launch_bounds__(256, 2) void k1_tc() {
    extern __shared__ char smraw[];
    const uint32_t smb = smem_u32(smraw);

    const int tid  = threadIdx.x;
    const int lane = tid & 31;
    const int wid  = tid >> 5;
    const int bn   = blockIdx.x;          // fastest: 4 bn CTAs share A rows
    const int bm   = blockIdx.y;
    const int wm   = (wid & 1) * 64;
    const int wn   = (wid >> 1) * 32;

    auto load_stage = [&](int c) {
        const uint32_t sa = smb + (c % K1_STAGES) * K1_STAGE;
        const uint32_t sb = sa + K1_A_SLOT;
        const __half* abase = g_xh + (size_t)bm * 128 * DDIM + c * 32;
        const __half* bbase = g_Bt + (size_t)bn * 128 * DDIM + c * 32;
        #pragma unroll
        for (int i = 0; i < 2; i++) {                  // A: 512 x 16B units
            int u = tid + 256 * i;
            int row = u >> 2, seg = u & 3;
            cp16(sa + SWZ64R(row * 64 + seg * 16),
                 abase + (size_t)row * DDIM + seg * 8);
        }
        #pragma unroll
        for (int i = 0; i < 2; i++) {                  // B: 512 x 16B units
            int u = tid + 256 * i;
            int row = u >> 2, seg = u & 3;
            cp16(sb + SWZ64R(row * 64 + seg * 16),
                 bbase + (size_t)row * DDIM + seg * 8);
        }
        CP_COMMIT();
    };

    float acc[4][4][4];
    #pragma unroll
    for (int t = 0; t < 4; t++)
        #pragma unroll
        for (int g = 0; g < 4; g++)
            #pragma unroll
            for (int e = 0; e < 4; e++) acc[t][g][e] = 0.0f;

    load_stage(0); load_stage(1); load_stage(2); load_stage(3); load_stage(4);

    const int a_m  = (lane & 15);
    const int a_kb = (lane >> 4) * 16;        // bytes within 32B k16 group
    const int b_n  = ((lane >> 4) << 3) + (lane & 7);
    const int b_kb = ((lane >> 3) & 1) * 16;

    for (int c = 0; c < NCHUNK1; ++c) {
        if (c <= NCHUNK1 - 5)      { CP_WAIT(4); }
        else if (c == NCHUNK1 - 4) { CP_WAIT(3); }
        else if (c == NCHUNK1 - 3) { CP_WAIT(2); }
        else if (c == NCHUNK1 - 2) { CP_WAIT(1); }
        else                       { CP_WAIT(0); }
        __syncthreads();
        if (c + 5 < NCHUNK1) load_stage(c + 5);

        const uint32_t sa = smb + (c % K1_STAGES) * K1_STAGE;
        const uint32_t sb = sa + K1_A_SLOT;

        #pragma unroll
        for (int kk = 0; kk < 2; kk++) {
            uint32_t af[4][4];
            #pragma unroll
            for (int t = 0; t < 4; t++) {
                int m = wm + t * 16 + a_m;
                ldsm4(af[t][0], af[t][1], af[t][2], af[t][3],
                      sa + SWZ64R(m * 64 + kk * 32 + a_kb));
            }
            uint32_t bf[2][4];
            #pragma unroll
            for (int g16 = 0; g16 < 2; g16++) {
                int n = wn + g16 * 16 + b_n;
                ldsm4(bf[g16][0], bf[g16][1], bf[g16][2], bf[g16][3],
                      sb + SWZ64R(n * 64 + kk * 32 + b_kb));
            }
            #pragma unroll
            for (int t = 0; t < 4; t++)
                #pragma unroll
                for (int g = 0; g < 4; g++)
                    mma16816h(acc[t][g], af[t], &bf[g >> 1][(g & 1) * 2]);
        }
    }
    __syncthreads();

    // ---- stage smooth_step(s) in fp32 smem [128][CS_ST] ----
    float* cs = (float*)smraw;
    const int r0 = lane >> 2;
    const int c0 = (lane & 3) * 2;
    #pragma unroll
    for (int t = 0; t < 4; t++) {
        #pragma unroll
        for (int g = 0; g < 4; g++) {
            int m = wm + t * 16 + r0;
            int n = wn + g * 8 + c0;
            cs[m * CS_ST + n]           = smooth_step(acc[t][g][0]);
            cs[m * CS_ST + n + 1]       = smooth_step(acc[t][g][1]);
            cs[(m + 8) * CS_ST + n]     = smooth_step(acc[t][g][2]);
            cs[(m + 8) * CS_ST + n + 1] = smooth_step(acc[t][g][3]);
        }
    }
    __syncthreads();

    // ---- tree routing: depth-first walk, 6 live partials, no spills ----
    {
        __half* mu_stage = (__half*)(smraw + CS_BYTES);   // [128][MU_ST]
        const int r  = tid & 127;
        const int th = tid >> 7;                          // 0 or 1
        const float* srow = cs + r * CS_ST + th * 64;
        __half* mrow = &mu_stage[r * MU_ST + th * 64];

        const float s0 = srow[0];
        #pragma unroll
        for (int i0 = 0; i0 < 2; i0++) {
            const float p1 = i0 ? (1.0f - s0) : s0;
            const float s1 = srow[1 + i0];
            #pragma unroll
            for (int i1 = 0; i1 < 2; i1++) {
                const float p2 = p1 * (i1 ? (1.0f - s1) : s1);
                const float s2 = srow[3 + i0 * 2 + i1];
                #pragma unroll
                for (int i2 = 0; i2 < 2; i2++) {
                    const float p3 = p2 * (i2 ? (1.0f - s2) : s2);
                    const float s3 = srow[7 + i0 * 4 + i1 * 2 + i2];
                    __half hb[8];
                    #pragma unroll
                    for (int i3 = 0; i3 < 2; i3++) {
                        const float p4 = p3 * (i3 ? (1.0f - s3) : s3);
                        const float s4 = srow[15 + i0 * 8 + i1 * 4 + i2 * 2 + i3];
                        #pragma unroll
                        for (int i4 = 0; i4 < 2; i4++) {
                            const float p5 = p4 * (i4 ? (1.0f - s4) : s4);
                            const float s5 = srow[31 + i0 * 16 + i1 * 8 + i2 * 4
                                                  + i3 * 2 + i4];
                            #pragma unroll
                            for (int i5 = 0; i5 < 2; i5++) {
                                const float p6 = p5 * (i5 ? (1.0f - s5) : s5);
                                hb[i3 * 4 + i4 * 2 + i5] = __float2half(p6);
                            }
                        }
                    }
                    *(uint4*)&mrow[(i0 * 4 + i1 * 2 + i2) * 8] = *(uint4*)hb;
                }
            }
        }
    }
    __syncthreads();

    // ---- coalesced mu store: per row 128 halves = 256B contiguous ----
    {
        __half* mu_stage = (__half*)(smraw + CS_BYTES);
        const int row  = tid >> 1;
        const int half = tid & 1;
        const uint4* src = (const uint4*)&mu_stage[row * MU_ST + half * 64];
        uint4* dst = (uint4*)(g_mu + ((size_t)bm * 128 + row) * NPAD
                              + bn * 128 + half * 64);
        #pragma unroll
        for (int j = 0; j < 8; j++) dst[j] = src[j];
    }
}

// ===========================================================================
// K3: leaf GEMM, M-tile 64 (grid 512) for finer wave balance + more latency
// hiding.  Warp tile 32x32 (acc 32 regs), 6-stage K32 pipeline, 12KB/stage.
// out[B x 128] = mu[B x 512] * LW[128 x 512]^T
// ===========================================================================
#define K3_STAGES 6
#define NCHUNK3   16
#define K3_A_SLOT 4096                            // 64 x 32 fp16 (64B rows)
#define K3_B_SLOT 8192                            // 128 x 32 fp16
#define K3_STAGE  (K3_A_SLOT + K3_B_SLOT)         // 12288
#define K3_SMEM_MAIN (K3_STAGES * K3_STAGE)       // 73728
#define K3_EPI   (64 * 132 * 4)                   // 33792
#define K3_SMEM (K3_SMEM_MAIN > K3_EPI ? K3_SMEM_MAIN : K3_EPI)

__global__ __launch_bounds__(256, 2) void k3_leaf(float* __restrict__ out) {
    extern __shared__ char smraw[];
    const uint32_t smb = smem_u32(smraw);

    const int tid  = threadIdx.x;
    const int lane = tid & 31;
    const int wid  = tid >> 5;
    const int bm   = blockIdx.x;                  // 0..511 (64 rows each)
    const int wm   = (wid & 1) * 32;
    const int wn   = (wid >> 1) * 32;

    auto load_stage = [&](int c) {
        const uint32_t sa = smb + (c % K3_STAGES) * K3_STAGE;
        const uint32_t sb = sa + K3_A_SLOT;
        const __half* abase = g_mu + (size_t)bm * 64 * NPAD + c * 32;
        const __half* bbase = g_LBh + c * 32;
        {                                              // A: 256 x 16B units
            int row = tid >> 2, seg = tid & 3;
            cp16(sa + SWZ64R(row * 64 + seg * 16),
                 abase + (size_t)row * NPAD + seg * 8);
        }
        #pragma unroll
        for (int i = 0; i < 2; i++) {                  // B: 512 x 16B units
            int u = tid + 256 * i;
            int row = u >> 2, seg = u & 3;
            cp16(sb + SWZ64R(row * 64 + seg * 16),
                 bbase + (size_t)row * NPAD + seg * 8);
        }
        CP_COMMIT();
    };

    float acc[2][4][4];
    #pragma unroll
    for (int t = 0; t < 2; t++)
        #pragma unroll
        for (int g = 0; g < 4; g++)
            #pragma unroll
            for (int e = 0; e < 4; e++) acc[t][g][e] = 0.0f;

    load_stage(0); load_stage(1); load_stage(2); load_stage(3); load_stage(4);

    const int a_m  = (lane & 15);
    const int a_kb = (lane >> 4) * 16;
    const int b_n  = ((lane >> 4) << 3) + (lane & 7);
    const int b_kb = ((lane >> 3) & 1) * 16;

    for (int c = 0; c < NCHUNK3; ++c) {
        if (c <= NCHUNK3 - 5)      { CP_WAIT(4); }
        else if (c == NCHUNK3 - 4) { CP_WAIT(3); }
        else if (c == NCHUNK3 - 3) { CP_WAIT(2); }
        else if (c == NCHUNK3 - 2) { CP_WAIT(1); }
        else                       { CP_WAIT(0); }
        __syncthreads();
        if (c + 5 < NCHUNK3) load_stage(c + 5);

        const uint32_t sa = smb + (c % K3_STAGES) * K3_STAGE;
        const uint32_t sb = sa + K3_A_SLOT;

        #pragma unroll
        for (int kk = 0; kk < 2; kk++) {
            uint32_t af[2][4];
            #pragma unroll
            for (int t = 0; t < 2; t++) {
                int m = wm + t * 16 + a_m;
                ldsm4(af[t][0], af[t][1], af[t][2], af[t][3],
                      sa + SWZ64R(m * 64 + kk * 32 + a_kb));
            }
            uint32_t bf[2][4];
            #pragma unroll
            for (int g16 = 0; g16 < 2; g16++) {
                int n = wn + g16 * 16 + b_n;
                ldsm4(bf[g16][0], bf[g16][1], bf[g16][2], bf[g16][3],
                      sb + SWZ64R(n * 64 + kk * 32 + b_kb));
            }
            #pragma unroll
            for (int t = 0; t < 2; t++)
                #pragma unroll
                for (int g = 0; g < 4; g++)
                    mma16816h(acc[t][g], af[t], &bf[g >> 1][(g & 1) * 2]);
        }
    }
    __syncthreads();

    float* cs = (float*)smraw;          // [64][132]
    const int r0 = lane >> 2;
    const int c0 = (lane & 3) * 2;
    #pragma unroll
    for (int t = 0; t < 2; t++) {
        #pragma unroll
        for (int g = 0; g < 4; g++) {
            int m = wm + t * 16 + r0;
            int n = wn + g * 8 + c0;
            cs[m * 132 + n]           = acc[t][g][0];
            cs[m * 132 + n + 1]       = acc[t][g][1];
            cs[(m + 8) * 132 + n]     = acc[t][g][2];
            cs[(m + 8) * 132 + n + 1] = acc[t][g][3];
        }
    }
    __syncthreads();

    {
        // 64 rows x 32 float4 = 2048 float4; 256 threads x 8
        #pragma unroll
        for (int i = 0; i < 8; i++) {
            int u = tid + 256 * i;
            int row = u >> 5, c4 = u & 31;
            float4 v = *(const float4*)&cs[row * 132 + c4 * 4];
            *(float4*)(out + ((size_t)bm * 64 + row) * ODIM + c4 * 4) = v;
        }
    }
}

// ===========================================================================
// Launch
// ===========================================================================
extern "C" void kernel_launch(void* const* d_in, const int* in_sizes, int n_in,
                              void* d_out, int out_size) {
    const float* x  = (const float*)d_in[0];   // [B, 1024]
    const float* nw = (const float*)d_in[1];   // [8, 1024, 63]
    const float* lw = (const float*)d_in[2];   // [8, 128, 64]
    float* out = (float*)d_out;                // [B, 128]

    int Brows = in_sizes[0] / DDIM;            // 32768

    cudaFuncSetAttribute(k1_tc,   cudaFuncAttributeMaxDynamicSharedMemorySize, K1_SMEM);
    cudaFuncSetAttribute(k3_leaf, cudaFuncAttributeMaxDynamicSharedMemorySize, K3_SMEM);

    prep   <<< GB + GL + GX2, 256 >>>(x, nw, lw);
    k1_tc  <<< dim3(NPAD / 128, Brows / 128), 256, K1_SMEM >>>();
    k3_leaf<<< Brows / 64, 256, K3_SMEM >>>(out);
}